// round 1
// baseline (speedup 1.0000x reference)
#include <cuda_runtime.h>
#include <math.h>

#define T_LEN  220500
#define NCH    64          // 32 batch * 2 channels
#define CHUNK  180
#define NCHUNK 1225        // 220500 / 180
#define NTASK  (NCH * NCHUNK)

// scratch: per-chunk boundary states (y[end], y[end-1]) for each filter
__device__ float  g_coef[10];       // [b0,b1,b2,a1,a2] low ; [b0,b1,b2,a1,a2] high (normalized by a0)
__device__ float2 g_stL[NTASK];
__device__ float2 g_stH[NTASK];

__global__ void coef_kernel(const int* __restrict__ sr_p,
                            const float* __restrict__ cl_p,
                            const float* __restrict__ ch_p) {
    if (threadIdx.x != 0) return;
    // robust scalar read: sample_rate may arrive as int32/int64 or float32
    int iv = *sr_p;
    double sr;
    if (iv > 0 && iv < 100000000) sr = (double)iv;
    else                          sr = (double)__int_as_float(iv);
    const double Q = 0.707;
    {
        double w0 = 2.0 * M_PI * (double)(*cl_p) / sr;
        double c  = cos(w0);
        double al = sin(w0) / (2.0 * Q);
        double a0 = 1.0 + al;
        g_coef[0] = (float)(((1.0 - c) * 0.5) / a0);
        g_coef[1] = (float)((1.0 - c) / a0);
        g_coef[2] = (float)(((1.0 - c) * 0.5) / a0);
        g_coef[3] = (float)((-2.0 * c) / a0);
        g_coef[4] = (float)((1.0 - al) / a0);
    }
    {
        double w0 = 2.0 * M_PI * (double)(*ch_p) / sr;
        double c  = cos(w0);
        double al = sin(w0) / (2.0 * Q);
        double a0 = 1.0 + al;
        g_coef[5] = (float)(((1.0 + c) * 0.5) / a0);
        g_coef[6] = (float)((-(1.0 + c)) / a0);
        g_coef[7] = (float)(((1.0 + c) * 0.5) / a0);
        g_coef[8] = (float)((-2.0 * c) / a0);
        g_coef[9] = (float)((1.0 - al) / a0);
    }
}

// one biquad step for both filters; ok = low - high
#define BSTEP(xk, ok) {                                          \
    float ffL = fmaf(bL0, (xk), fmaf(bL1, xm1, bL2 * xm2));      \
    float ffH = fmaf(bH0, (xk), fmaf(bH1, xm1, bH2 * xm2));      \
    float yL  = fmaf(nL1, l1, fmaf(nL2, l2, ffL));               \
    float yH  = fmaf(nH1, h1, fmaf(nH2, h2, ffH));               \
    (ok) = yL - yH;                                              \
    l2 = l1; l1 = yL; h2 = h1; h1 = yH;                          \
    xm2 = xm1; xm1 = (xk); }

// Pass 1 (FINAL=false): zero-init recurrence per chunk, emit end states.
// Pass 3 (FINAL=true):  exact recurrence from chained init states, write output.
template <bool FINAL>
__global__ __launch_bounds__(128)
void chunk_kernel(const float* __restrict__ x, float* __restrict__ out) {
    int j = blockIdx.x * blockDim.x + threadIdx.x;
    if (j >= NCHUNK) return;
    int chn = blockIdx.y;

    float bL0 = g_coef[0], bL1 = g_coef[1], bL2 = g_coef[2];
    float nL1 = -g_coef[3], nL2 = -g_coef[4];
    float bH0 = g_coef[5], bH1 = g_coef[6], bH2 = g_coef[7];
    float nH1 = -g_coef[8], nH2 = -g_coef[9];

    size_t base = (size_t)chn * T_LEN + (size_t)j * CHUNK;
    const float* xb = x + base;

    float xm1 = 0.f, xm2 = 0.f;
    if (j > 0) { xm1 = xb[-1]; xm2 = xb[-2]; }

    int sidx = chn * NCHUNK + j;
    float l1, l2, h1, h2;
    if (FINAL) {
        float2 sL = g_stL[sidx];
        float2 sH = g_stH[sidx];
        l1 = sL.x; l2 = sL.y; h1 = sH.x; h2 = sH.y;
    } else {
        l1 = l2 = h1 = h2 = 0.f;
    }

    float* ob = out + base;
#pragma unroll 1
    for (int k = 0; k < CHUNK; k += 4) {
        float4 xv = *reinterpret_cast<const float4*>(xb + k);
        float4 ov;
        BSTEP(xv.x, ov.x);
        BSTEP(xv.y, ov.y);
        BSTEP(xv.z, ov.z);
        BSTEP(xv.w, ov.w);
        if (FINAL) *reinterpret_cast<float4*>(ob + k) = ov;
    }

    if (!FINAL) {
        g_stL[sidx] = make_float2(l1, l2);
        g_stH[sidx] = make_float2(h1, h2);
    }
}

// Pass 2: chain boundary states across chunks.  s_j = e_j + M * s_{j-1},
// M = companion(a1,a2)^CHUNK, computed from the homogeneous recurrence.
// Slot j is overwritten with the INITIAL state for chunk j (i.e. s_{j-1}).
__global__ void chain_kernel() {
    int tid = threadIdx.x;
    if (tid >= 2 * NCH) return;
    int filt = tid >> 6;         // 0 = low, 1 = high
    int chn  = tid & (NCH - 1);

    float na1 = -g_coef[filt * 5 + 3];
    float na2 = -g_coef[filt * 5 + 4];

    // homogeneous responses: u from (y[-1]=1, y[-2]=0), v from (0, 1)
    float u1 = 1.f, u2 = 0.f, v1 = 0.f, v2 = 1.f;
#pragma unroll 1
    for (int n = 0; n < CHUNK; n++) {
        float yu = fmaf(na1, u1, na2 * u2);
        float yv = fmaf(na1, v1, na2 * v2);
        u2 = u1; u1 = yu;
        v2 = v1; v1 = yv;
    }
    // now (u1,v1;u2,v2) maps (y[-1],y[-2]) -> (y[L-1],y[L-2])

    float2* st = (filt ? g_stH : g_stL) + (size_t)chn * NCHUNK;
    float sx = 0.f, sy = 0.f;
#pragma unroll 1
    for (int j = 0; j < NCHUNK; j++) {
        float2 e = st[j];
        st[j] = make_float2(sx, sy);          // init state for chunk j
        float nsx = fmaf(u1, sx, fmaf(v1, sy, e.x));
        float nsy = fmaf(u2, sx, fmaf(v2, sy, e.y));
        sx = nsx; sy = nsy;
    }
}

extern "C" void kernel_launch(void* const* d_in, const int* in_sizes, int n_in,
                              void* d_out, int out_size) {
    const float* audio = (const float*)d_in[0];
    const int*   sr    = (const int*)d_in[1];
    const float* cl    = (const float*)d_in[2];
    const float* ch    = (const float*)d_in[3];
    float* out = (float*)d_out;

    coef_kernel<<<1, 32>>>(sr, cl, ch);

    dim3 grid((NCHUNK + 127) / 128, NCH);
    chunk_kernel<false><<<grid, 128>>>(audio, out);
    chain_kernel<<<1, 128>>>();
    chunk_kernel<true><<<grid, 128>>>(audio, out);
}

// round 2
// speedup vs baseline: 13.8263x; 13.8263x over previous
#include <cuda_runtime.h>
#include <math.h>

#define T_LEN      220500
#define NCH        64                 // 32 batch * 2 channels
#define CHUNK      84
#define NCHUNK_CH  2625               // 220500 / 84
#define NCHUNK_TOT (NCH * NCHUNK_CH)  // 168000
#define TOTAL_F4   3528000            // 14,112,000 / 4
#define BT         128
#define SMEM_F     (BT * CHUNK)       // 10752 floats = 43008 B
#define F4_PER_BLK (SMEM_F / 4)       // 2688
#define SEG        11                 // 256 * 11 = 2816 >= 2625

__device__ float  g_coef[10];  // [b0,b1,b2,a1,a2] low ; same high (normalized by a0)
__device__ float2 g_stL[NCHUNK_TOT];
__device__ float2 g_stH[NCHUNK_TOT];

__global__ void coef_kernel(const int* __restrict__ sr_p,
                            const float* __restrict__ cl_p,
                            const float* __restrict__ ch_p) {
    if (threadIdx.x != 0) return;
    int iv = *sr_p;
    double sr;
    if (iv > 0 && iv < 100000000) sr = (double)iv;
    else                          sr = (double)__int_as_float(iv);
    const double Q = 0.707;
    {
        double w0 = 2.0 * M_PI * (double)(*cl_p) / sr;
        double c  = cos(w0);
        double al = sin(w0) / (2.0 * Q);
        double a0 = 1.0 + al;
        g_coef[0] = (float)(((1.0 - c) * 0.5) / a0);
        g_coef[1] = (float)((1.0 - c) / a0);
        g_coef[2] = (float)(((1.0 - c) * 0.5) / a0);
        g_coef[3] = (float)((-2.0 * c) / a0);
        g_coef[4] = (float)((1.0 - al) / a0);
    }
    {
        double w0 = 2.0 * M_PI * (double)(*ch_p) / sr;
        double c  = cos(w0);
        double al = sin(w0) / (2.0 * Q);
        double a0 = 1.0 + al;
        g_coef[5] = (float)(((1.0 + c) * 0.5) / a0);
        g_coef[6] = (float)((-(1.0 + c)) / a0);
        g_coef[7] = (float)(((1.0 + c) * 0.5) / a0);
        g_coef[8] = (float)((-2.0 * c) / a0);
        g_coef[9] = (float)((1.0 - al) / a0);
    }
}

#define BSTEP(xk, ok) {                                          \
    float ffL = fmaf(bL0, (xk), fmaf(bL1, xm1, bL2 * xm2));      \
    float ffH = fmaf(bH0, (xk), fmaf(bH1, xm1, bH2 * xm2));      \
    float yL  = fmaf(nL1, l1, fmaf(nL2, l2, ffL));               \
    float yH  = fmaf(nH1, h1, fmaf(nH2, h2, ffH));               \
    (ok) = yL - yH;                                              \
    l2 = l1; l1 = yL; h2 = h1; h1 = yH;                          \
    xm2 = xm1; xm1 = (xk); }

// Pass 1 (FINAL=false): zero-init recurrence per chunk, emit end states only.
// Pass 3 (FINAL=true):  exact recurrence from chained init states, write output.
// Input staged coalesced into smem; FINAL output written back to smem then
// stored coalesced. Chunks are a flat partition (channel boundaries align).
template <bool FINAL>
__global__ __launch_bounds__(BT)
void chunk_kernel(const float* __restrict__ x, float* __restrict__ out) {
    __shared__ float sbuf[SMEM_F];
    int t = threadIdx.x;
    size_t base4 = (size_t)blockIdx.x * F4_PER_BLK;
    const float4* xg4 = (const float4*)x;
    float4* s4 = (float4*)sbuf;
#pragma unroll
    for (int i = 0; i < F4_PER_BLK / BT; i++) {
        size_t idx = base4 + t + (size_t)i * BT;
        if (idx < TOTAL_F4) s4[t + i * BT] = xg4[idx];
    }
    __syncthreads();

    int g = blockIdx.x * BT + t;       // global chunk id
    bool valid = g < NCHUNK_TOT;

    float xm1 = 0.f, xm2 = 0.f;
    if (valid && (g % NCHUNK_CH) != 0) {
        if (t == 0) {
            size_t s0 = (size_t)g * CHUNK;
            xm1 = x[s0 - 1];
            xm2 = x[s0 - 2];
        } else {
            xm1 = sbuf[t * CHUNK - 1];
            xm2 = sbuf[t * CHUNK - 2];
        }
    }
    __syncthreads();   // history reads done before in-place overwrite (FINAL)

    if (valid) {
        float bL0 = g_coef[0], bL1 = g_coef[1], bL2 = g_coef[2];
        float nL1 = -g_coef[3], nL2 = -g_coef[4];
        float bH0 = g_coef[5], bH1 = g_coef[6], bH2 = g_coef[7];
        float nH1 = -g_coef[8], nH2 = -g_coef[9];

        float l1, l2, h1, h2;
        if (FINAL) {
            float2 sL = g_stL[g];
            float2 sH = g_stH[g];
            l1 = sL.x; l2 = sL.y; h1 = sH.x; h2 = sH.y;
        } else {
            l1 = l2 = h1 = h2 = 0.f;
        }

        float* cb = sbuf + t * CHUNK;
#pragma unroll 1
        for (int k = 0; k < CHUNK; k += 4) {
            float4 xv = *reinterpret_cast<const float4*>(cb + k);
            float4 ov;
            BSTEP(xv.x, ov.x);
            BSTEP(xv.y, ov.y);
            BSTEP(xv.z, ov.z);
            BSTEP(xv.w, ov.w);
            if (FINAL) *reinterpret_cast<float4*>(cb + k) = ov;
        }
        if (!FINAL) {
            g_stL[g] = make_float2(l1, l2);
            g_stH[g] = make_float2(h1, h2);
        }
    }

    if (FINAL) {
        __syncthreads();
        float4* og4 = (float4*)out;
#pragma unroll
        for (int i = 0; i < F4_PER_BLK / BT; i++) {
            size_t idx = base4 + t + (size_t)i * BT;
            if (idx < TOTAL_F4) og4[idx] = s4[t + i * BT];
        }
    }
}

// Pass 2: affine prefix scan of boundary states.  s_j = A*s_{j-1} + e_j with
// A = companion(a1,a2)^CHUNK (constant). One block per (channel, filter).
// Each thread serially folds SEG chunks; Kogge-Stone combines 256 segments
// in smem using powers of A^SEG; then each thread replays its segment,
// overwriting slot j with the INITIAL state for chunk j.
__global__ __launch_bounds__(256)
void chain_kernel() {
    int chn  = blockIdx.x >> 1;
    int filt = blockIdx.x & 1;
    int t = threadIdx.x;

    float na1 = -g_coef[filt * 5 + 3];
    float na2 = -g_coef[filt * 5 + 4];

    // A = per-sample companion matrix ^ CHUNK, columns (u1,u2), (v1,v2)
    float u1 = 1.f, u2 = 0.f, v1 = 0.f, v2 = 1.f;
#pragma unroll 1
    for (int n = 0; n < CHUNK; n++) {
        float yu = fmaf(na1, u1, na2 * u2);
        float yv = fmaf(na1, v1, na2 * v2);
        u2 = u1; u1 = yu;
        v2 = v1; v1 = yv;
    }

    float2* st = (filt ? g_stH : g_stL) + (size_t)chn * NCHUNK_CH;

    // local fold of SEG chunks (zero-init), keep e's in registers
    float2 e[SEG];
    int j0 = t * SEG;
    float fx = 0.f, fy = 0.f;
#pragma unroll
    for (int k = 0; k < SEG; k++) {
        int j = j0 + k;
        float2 ee = (j < NCHUNK_CH) ? st[j] : make_float2(0.f, 0.f);
        e[k] = ee;
        float nx = fmaf(u1, fx, fmaf(v1, fy, ee.x));
        float ny = fmaf(u2, fx, fmaf(v2, fy, ee.y));
        fx = nx; fy = ny;
    }

    // B = A^SEG
    float b00 = u1, b01 = v1, b10 = u2, b11 = v2;
#pragma unroll
    for (int k = 1; k < SEG; k++) {
        float n00 = fmaf(u1, b00, v1 * b10);
        float n01 = fmaf(u1, b01, v1 * b11);
        float n10 = fmaf(u2, b00, v2 * b10);
        float n11 = fmaf(u2, b01, v2 * b11);
        b00 = n00; b01 = n01; b10 = n10; b11 = n11;
    }

    __shared__ float2 S[256];
    S[t] = make_float2(fx, fy);
    __syncthreads();

#pragma unroll
    for (int o = 1; o < 256; o <<= 1) {
        float2 lo = (t >= o) ? S[t - o] : make_float2(0.f, 0.f);
        float2 me = S[t];
        __syncthreads();
        if (t >= o) {
            me.x = fmaf(b00, lo.x, fmaf(b01, lo.y, me.x));
            me.y = fmaf(b10, lo.x, fmaf(b11, lo.y, me.y));
        }
        S[t] = me;
        // B = B*B
        float n00 = fmaf(b00, b00, b01 * b10);
        float n01 = fmaf(b00, b01, b01 * b11);
        float n10 = fmaf(b10, b00, b11 * b10);
        float n11 = fmaf(b10, b01, b11 * b11);
        b00 = n00; b01 = n01; b10 = n10; b11 = n11;
        __syncthreads();
    }

    float2 prev = (t > 0) ? S[t - 1] : make_float2(0.f, 0.f);
    float sx = prev.x, sy = prev.y;
#pragma unroll
    for (int k = 0; k < SEG; k++) {
        int j = j0 + k;
        if (j < NCHUNK_CH) {
            st[j] = make_float2(sx, sy);       // init state for chunk j
            float nx = fmaf(u1, sx, fmaf(v1, sy, e[k].x));
            float ny = fmaf(u2, sx, fmaf(v2, sy, e[k].y));
            sx = nx; sy = ny;
        }
    }
}

extern "C" void kernel_launch(void* const* d_in, const int* in_sizes, int n_in,
                              void* d_out, int out_size) {
    const float* audio = (const float*)d_in[0];
    const int*   sr    = (const int*)d_in[1];
    const float* cl    = (const float*)d_in[2];
    const float* ch    = (const float*)d_in[3];
    float* out = (float*)d_out;

    coef_kernel<<<1, 32>>>(sr, cl, ch);

    int nblk = (NCHUNK_TOT + BT - 1) / BT;   // 1313
    chunk_kernel<false><<<nblk, BT>>>(audio, out);
    chain_kernel<<<2 * NCH, 256>>>();
    chunk_kernel<true><<<nblk, BT>>>(audio, out);
}